// round 17
// baseline (speedup 1.0000x reference)
#include <cuda_runtime.h>
#include <cuda_fp16.h>
#include <math_constants.h>

#define B    32
#define T    336
#define C    7
#define NSH  5
#define NG   4
#define NF   140            // 4 groups * 5 * 7
#define OUTC 10
#define NWORKBLK (B * C * NSH)      // 1120 worker blocks (bc, nn), 8 warps
#define NHEAD    21                 // 20 dot blocks + 1 loss block
#define NTHR     256

// offsets in d_out (floats): out[320] | dists[4480] | probs[4480] | loss[1]
#define OFF_OUT   0
#define OFF_DIST  320
#define OFF_PROB  (320 + B*NF)
#define OFF_LOSS  (320 + 2*B*NF)

#define SXN   356          // fp32 staging, zero-padded
#define PAIRN 176          // half2 pair arrays length
// swh offsets (half2 entries, even): g0@0(34) g1@64(68) g2@160(101) g3@288(168)
#define SWH_TOT 456

__device__ int g_ctr  = 0;   // worker blocks completed
__device__ int g_ctr2 = 0;   // head blocks completed

__constant__ float c_invL[4] = { 1.f/34.f, 1.f/68.f, 1.f/101.f, 1.f/168.f };

// ---------------------------------------------------------------------------
// Wide fp16 sliding-min sub-token: lane owns W = 2*NA consecutive windows at
// base j = W*(ll + 32*p0), clamped even (duplicates min-safe, invalid windows
// masked to +inf). Acc n (half2) covers windows (j+2n, j+2n+1):
//   l=2h -> she[e+n+h],  l=2h+1 -> sho[e+n+h]
// Per h-step: 1 she + 1 sho rolling LDS.32 + 1 broadcast LDS.64 (w pair) feed
// all NA accumulators (6*NA H-ops). Chunks (16 l-steps) flushed to fp32.
// ---------------------------------------------------------------------------
template<int L, int NA>
__device__ __forceinline__ void run_wide(const __half2* __restrict__ she,
                                         const __half2* __restrict__ sho,
                                         const __half2* __restrict__ swh,
                                         int ll, int p0,
                                         unsigned* __restrict__ sminp) {
    constexpr int TW   = T - L + 1;
    constexpr int W    = 2 * NA;
    constexpr int JC   = (TW - W + 2) & ~1;   // even clamp base, reaches TW-1
    constexpr int H    = L / 2;
    constexpr int NB   = H / 8;
    constexpr int HREM = H - NB * 8;

    const __half hz   = __ushort_as_half((unsigned short)0x0000);
    const __half hinf = __ushort_as_half((unsigned short)0x7C00);

    int j = W * (ll + 32 * p0);
    if (j > JC) j = JC;                        // duplicate work, min-safe
    const int e = j >> 1;

    __half2 A[NA], I[NA], E[NA + 1], O[NA + 1];
    float2  f[NA];
    #pragma unroll
    for (int n = 0; n < NA; n++) {
        I[n] = __halves2half2((j + 2 * n     < TW) ? hz : hinf,
                              (j + 2 * n + 1 < TW) ? hz : hinf);
        A[n] = I[n];
        f[n] = make_float2(0.f, 0.f);
    }
    #pragma unroll
    for (int n = 0; n <= NA; n++) { E[n] = she[e + n]; O[n] = sho[e + n]; }

    int h = 0;
    #pragma unroll 1
    for (int hb = 0; hb < NB; hb++) {
        #pragma unroll
        for (int hh = 0; hh < 8; hh++) {
            const uint2 wv = *reinterpret_cast<const uint2*>(swh + 2 * (h + hh));
            const __half2 w0 = *reinterpret_cast<const __half2*>(&wv.x);
            const __half2 w1 = *reinterpret_cast<const __half2*>(&wv.y);
            #pragma unroll
            for (int n = 0; n < NA; n++) {
                A[n] = __hadd2(A[n], __habs2(__hsub2(E[n], w0)));
                A[n] = __hadd2(A[n], __habs2(__hsub2(O[n], w1)));
            }
            #pragma unroll
            for (int n = 0; n < NA; n++) { E[n] = E[n + 1]; O[n] = O[n + 1]; }
            const int idx = e + h + hh + NA + 1;
            E[NA] = she[idx];
            O[NA] = sho[idx];
        }
        h += 8;
        #pragma unroll
        for (int n = 0; n < NA; n++) {         // chunk flush to fp32
            const float2 t = __half22float2(A[n]);
            f[n].x += t.x; f[n].y += t.y;
            A[n] = I[n];
        }
    }
    #pragma unroll
    for (int hh = 0; hh < HREM; hh++) {        // tail h-steps (< 8)
        const uint2 wv = *reinterpret_cast<const uint2*>(swh + 2 * (h + hh));
        const __half2 w0 = *reinterpret_cast<const __half2*>(&wv.x);
        const __half2 w1 = *reinterpret_cast<const __half2*>(&wv.y);
        #pragma unroll
        for (int n = 0; n < NA; n++) {
            A[n] = __hadd2(A[n], __habs2(__hsub2(E[n], w0)));
            A[n] = __hadd2(A[n], __habs2(__hsub2(O[n], w1)));
        }
        #pragma unroll
        for (int n = 0; n < NA; n++) { E[n] = E[n + 1]; O[n] = O[n + 1]; }
        const int idx = e + h + hh + NA + 1;
        E[NA] = she[idx];
        O[NA] = sho[idx];
    }
    if (L & 1) {                               // last even step l = L-1
        const __half2 w0 = swh[L - 1];
        #pragma unroll
        for (int n = 0; n < NA; n++)
            A[n] = __hadd2(A[n], __habs2(__hsub2(E[n], w0)));
    }

    float mn = CUDART_INF_F;
    #pragma unroll
    for (int n = 0; n < NA; n++) {             // final flush + lane min
        const float2 t = __half22float2(A[n]);
        f[n].x += t.x; f[n].y += t.y;
        mn = fminf(mn, fminf(f[n].x, f[n].y));
    }
    #pragma unroll
    for (int o = 16; o > 0; o >>= 1)
        mn = fminf(mn, __shfl_xor_sync(0xffffffffu, mn, o));
    if (ll == 0) atomicMin(sminp, __float_as_uint(mn));   // d>=0: bits monotone
}

// ---------------------------------------------------------------------------
// Single launch. grid.x = 1120 workers + 21 heads, 256 threads (8 warps).
// 8 balanced warp tokens (cost = H*(6*NA+4)):
//   t0-2: g3 NA=1 p0/p1/p2 (840)   t3-4: g2 NA=2 p0/p1 (800)
//   t5-6: g1 NA=3 p0/p1   (748)    t7  : g0 NA=3 p0+p1 (374+374)
// Token-to-warp rotated by bid.
// ---------------------------------------------------------------------------
__global__ __launch_bounds__(NTHR, 5) void fused_kernel(
        const float* __restrict__ x,
        const float* __restrict__ w0,
        const float* __restrict__ w1,
        const float* __restrict__ w2,
        const float* __restrict__ w3,
        const float* __restrict__ Wout,
        float* __restrict__ d_out) {
    const int bid = blockIdx.x;
    const int tid = threadIdx.x;          // 256

    if (bid < NWORKBLK) {
        // ================= WORKER =================
        const int nn = bid % NSH;
        const int bc = bid / NSH;
        const int b  = bc / C;
        const int ch = bc % C;
        const int wp = tid >> 5;             // warp 0..7
        const int ll = tid & 31;

        __shared__ __align__(16) float   sxf[SXN];
        __shared__ __align__(16) __half2 she[PAIRN];
        __shared__ __align__(16) __half2 sho[PAIRN];
        __shared__ __align__(16) __half2 swh[SWH_TOT];
        __shared__ float red[16];
        __shared__ unsigned smin[4];

        // ---- normalization: one pass sum + sumsq over the (b,ch) row ----
        const float* xrow = x + (size_t)b * T * C + ch;   // stride C over t
        float vals[2];
        float s = 0.f, ss = 0.f;
        #pragma unroll
        for (int i = 0; i < 2; i++) {
            int t = tid + i * NTHR;
            float v = (t < T) ? xrow[(size_t)t * C] : 0.f;
            vals[i] = v;
            s += v;
            ss += v * v;
        }
        #pragma unroll
        for (int o = 16; o > 0; o >>= 1) {
            s  += __shfl_xor_sync(0xffffffffu, s, o);
            ss += __shfl_xor_sync(0xffffffffu, ss, o);
        }
        if (ll == 0) { red[wp] = s; red[8 + wp] = ss; }
        if (tid < 4) smin[tid] = 0x7f800000u;   // +inf bits

        // ---- warps 0-3 convert+store shapelet row of group wp ----
        if (wp < 4) {
            int L, goff;
            const float* wg;
            switch (wp) {
                case 0:  L = 34;  goff = 0;   wg = w0; break;
                case 1:  L = 68;  goff = 64;  wg = w1; break;
                case 2:  L = 101; goff = 160; wg = w2; break;
                default: L = 168; goff = 288; wg = w3; break;
            }
            const float* wrow = wg + (size_t)(nn * C + ch) * L;
            for (int i = ll; i < L; i += 32)
                swh[goff + i] = __float2half2_rn(wrow[i]);
        }

        __syncthreads();
        float stot = 0.f, sstot = 0.f;
        #pragma unroll
        for (int i = 0; i < 8; i++) { stot += red[i]; sstot += red[8 + i]; }
        const float mu  = stot * (1.0f / (float)T);
        const float var = (sstot - (float)T * mu * mu) * (1.0f / (float)(T - 1));
        const float inv = 1.0f / (sqrtf(fmaxf(var, 0.f)) + 1e-8f);

        #pragma unroll
        for (int i = 0; i < 2; i++) {
            int t = tid + i * NTHR;
            if (t < T) sxf[t] = (vals[i] - mu) * inv;
        }
        for (int i = T + tid; i < SXN; i += NTHR) sxf[i] = 0.f;  // zero pads
        __syncthreads();

        // ---- build fp16 pair arrays ----
        for (int i = tid; i < PAIRN; i += NTHR) {
            she[i] = __floats2half2_rn(sxf[2 * i],     sxf[2 * i + 1]);
            sho[i] = __floats2half2_rn(sxf[2 * i + 1], sxf[2 * i + 2]);
        }
        __syncthreads();

        // ---- 8 balanced sub-tokens, rotated across blocks ----
        switch ((wp + bid) & 7) {
            case 0:  run_wide<168, 1>(she, sho, swh + 288, ll, 0, &smin[3]); break;
            case 1:  run_wide<168, 1>(she, sho, swh + 288, ll, 1, &smin[3]); break;
            case 2:  run_wide<168, 1>(she, sho, swh + 288, ll, 2, &smin[3]); break;
            case 3:  run_wide<101, 2>(she, sho, swh + 160, ll, 0, &smin[2]); break;
            case 4:  run_wide<101, 2>(she, sho, swh + 160, ll, 1, &smin[2]); break;
            case 5:  run_wide<68,  3>(she, sho, swh + 64,  ll, 0, &smin[1]); break;
            case 6:  run_wide<68,  3>(she, sho, swh + 64,  ll, 1, &smin[1]); break;
            default:
                run_wide<34,  3>(she, sho, swh + 0,   ll, 0, &smin[0]);
                run_wide<34,  3>(she, sho, swh + 0,   ll, 1, &smin[0]);
                break;
        }
        __syncthreads();

        if (tid < 4) {                      // one thread per g writes results
            const float dmin = __uint_as_float(smin[tid]) * c_invL[tid];
            const int idx = b * NF + tid * (NSH * C) + nn * C + ch;
            d_out[OFF_DIST + idx] = dmin;
            d_out[OFF_PROB + idx] = expf(-dmin * dmin);   // EPS_GATE = 1
        }
        __syncthreads();
        if (tid == 0) {
            __threadfence();
            atomicAdd(&g_ctr, 1);           // publish this block's 4 results
        }
    } else {
        // ================= HEAD =================
        const int h = bid - NWORKBLK;    // 0..20

        if (tid == 0) {
            while (atomicAdd(&g_ctr, 0) < NWORKBLK) __nanosleep(64);
        }
        __syncthreads();
        __threadfence();                  // acquire published probs

        if (h < 20) {
            // 16 dots per block; warp wp does 2 dots
            const int wp = tid >> 5;
            const int ln = tid & 31;
            const float* probs = d_out + OFF_PROB;
            #pragma unroll
            for (int d = 0; d < 2; d++) {
                const int dot = h * 16 + wp * 2 + d;     // < 320
                const int bb = dot / OUTC;
                const int o  = dot % OUTC;
                const float* p  = probs + bb * NF;
                const float* wv = Wout + o * NF;
                float v = 0.f;
                #pragma unroll
                for (int f = ln; f < NF; f += 32) v += p[f] * wv[f];
                #pragma unroll
                for (int off = 16; off > 0; off >>= 1)
                    v += __shfl_xor_sync(0xffffffffu, v, off);
                if (ln == 0) d_out[OFF_OUT + dot] = v;
            }
        } else {
            // loss = 0.1 * mean|Wout|
            __shared__ float sred[8];
            float v = 0.f;
            for (int i = tid; i < OUTC * NF; i += NTHR) v += fabsf(Wout[i]);
            #pragma unroll
            for (int off = 16; off > 0; off >>= 1)
                v += __shfl_xor_sync(0xffffffffu, v, off);
            if ((tid & 31) == 0) sred[tid >> 5] = v;
            __syncthreads();
            if (tid == 0) {
                float tot = 0.f;
                #pragma unroll
                for (int i = 0; i < 8; i++) tot += sred[i];
                d_out[OFF_LOSS] = 0.1f * tot / (float)(OUTC * NF);
            }
        }

        __syncthreads();
        if (tid == 0) {
            int v = atomicAdd(&g_ctr2, 1);
            if (v == NHEAD - 1) {
                // last head block resets counters for the next graph replay
                atomicExch(&g_ctr, 0);
                atomicExch(&g_ctr2, 0);
            }
        }
    }
}

// ---------------------------------------------------------------------------
extern "C" void kernel_launch(void* const* d_in, const int* in_sizes, int n_in,
                              void* d_out, int out_size) {
    const float* x    = (const float*)d_in[0];
    const float* w0   = (const float*)d_in[1];
    const float* w1   = (const float*)d_in[2];
    const float* w2   = (const float*)d_in[3];
    const float* w3   = (const float*)d_in[4];
    const float* Wout = (const float*)d_in[5];
    float* out = (float*)d_out;

    fused_kernel<<<NWORKBLK + NHEAD, NTHR>>>(x, w0, w1, w2, w3, Wout, out);
}